// round 17
// baseline (speedup 1.0000x reference)
#include <cuda_runtime.h>
#include <cuda_fp16.h>
#include <math.h>
#include <stdint.h>

#define NN 170
#define NKP 192            // padded node dim (K of spatial GEMM, multiple of 64)
#define TT 12
#define BB 32
#define DD 120
#define HH 8
#define HD 15
#define FF 2048
#define BT (BB*TT)          // 384
#define MTOK (BB*TT*NN)     // 65280 = 510*128
#define MSP (BT*DD)         // 46080 = 360*128
#define XK 384              // padded xcat K (multiple of 64)

#define FLAG_BIAS  1
#define FLAG_RELU  2
#define FLAG_T2    4        // epilogue: v = 2*acc - (Xh+Xl)

// ------------------------- static device scratch (zero-initialized) --------
__device__ float g_A[3*NN*NN];
__device__ float g_rs0[3*NN];
__device__ float g_rs1[3*NN];

__device__ __align__(16) __half g_Lh[3*NKP*NKP];            // rows/cols padded, hi only
__device__ __align__(16) __half g_xth[(size_t)MSP*NKP];
__device__ __align__(16) __half g_xtl[(size_t)MSP*NKP];     // for T2 fp32 reconstruction
__device__ __align__(16) __half g_t1h[(size_t)3*MSP*NKP];   // per-branch, hi only
__device__ __align__(16) __half g_xcath[(size_t)3*MTOK*XK]; // per-branch; cols 360..383 zero
__device__ __align__(16) __half g_oah[(size_t)MTOK*128];    // attn out, hi only
__device__ __align__(16) __half g_o1h[(size_t)MTOK*128];    // LN1 out fp16
__device__ __align__(16) __half g_hidh[(size_t)MTOK*FF];    // hidden, hi only
__device__ __align__(16) __half g_qkvh[(size_t)3*MTOK*DD];  // q/k/v fp16
// weights
__device__ __align__(16) __half g_wqh[3*128*XK];
__device__ __align__(16) __half g_owh[128*128];
__device__ __align__(16) __half g_owl[128*128];
__device__ __align__(16) __half g_w1h[(size_t)FF*128];
__device__ __align__(16) __half g_w2h[(size_t)128*FF];
__device__ float g_out1f[(size_t)MTOK*DD];

// ------------------------- helpers -------------------------
__device__ __forceinline__ void hsplit(float v, __half &h, __half &l) {
    h = __float2half_rn(v);
    l = __float2half_rn(v - __half2float(h));
}
__device__ __forceinline__ uint32_t smem_u32(const void* p) {
    uint32_t a;
    asm("{ .reg .u64 t; cvta.to.shared.u64 t, %1; cvt.u32.u64 %0, t; }" : "=r"(a) : "l"(p));
    return a;
}
__device__ __forceinline__ void ldm4(uint32_t (&d)[4], uint32_t addr) {
    asm volatile("ldmatrix.sync.aligned.m8n8.x4.shared.b16 {%0,%1,%2,%3}, [%4];"
                 : "=r"(d[0]), "=r"(d[1]), "=r"(d[2]), "=r"(d[3]) : "r"(addr));
}
__device__ __forceinline__ void mma16816(float (&c)[4], const uint32_t (&a)[4],
                                         uint32_t b0, uint32_t b1) {
    asm volatile("mma.sync.aligned.m16n8k16.row.col.f32.f16.f16.f32 "
                 "{%0,%1,%2,%3}, {%4,%5,%6,%7}, {%8,%9}, {%0,%1,%2,%3};"
                 : "+f"(c[0]), "+f"(c[1]), "+f"(c[2]), "+f"(c[3])
                 : "r"(a[0]), "r"(a[1]), "r"(a[2]), "r"(a[3]), "r"(b0), "r"(b1));
}

// ------------------------- HMMA fp16 GEMM ------------------------------
// D[M,N] = sum_k A[m,k]*B[n,k]; A hi-only (M x K, lda).
// NPASS=2: Ah*Bh + Ah*Bl. NPASS=1: Ah*Bh only.
// BK in {32,64}. K%BK==0, M%128==0. Batched over blockIdx.z via strides.
// If lng != nullptr: fused residual+LayerNorm epilogue over the CTA's rows
// (requires single col tile, Nout<=121): out = LN(lnx_row + acc + bias).
template<int BN, int NPASS, int BK>
__global__ __launch_bounds__(256) void hmma_fp16(
        const __half* __restrict__ Ah, int lda,
        const __half* __restrict__ Bh, const __half* __restrict__ Bl, int ldb,
        int K,
        float* __restrict__ Cf, __half* __restrict__ Ch,
        int ldc, int Nout,
        const float* __restrict__ bias, int flags,
        const __half* __restrict__ Xh, const __half* __restrict__ Xl,
        __half* __restrict__ XCh, int xoff,
        long astride, long bstride, long cstride, int biasstride, long xcstride,
        int swapxy,
        const float* __restrict__ lnx, const float* __restrict__ lng,
        const float* __restrict__ lnb, float* __restrict__ lnoutF,
        __half* __restrict__ lnoutH)
{
    constexpr int KR = BK / 16;
    constexpr int RU = 2*KR + 1;            // 16B units per smem row
    constexpr int A16u = 128*RU;
    constexpr int B16u = BN*RU;
    constexpr int STAGE_BYTES = (A16u + NPASS*B16u) * 16;
    constexpr int NBA = KR;
    constexpr int NBB = (BN*2*KR*NPASS)/256;
    constexpr int WN = BN / 2;
    constexpr int NP = WN / 16;
    constexpr int BU = BN*2*KR;

    extern __shared__ __align__(16) char smem[];
    const uint32_t sbase = smem_u32(smem);
    const int tid = threadIdx.x;
    const int lane = tid & 31;
    const int wid = tid >> 5;
    const int wm = wid & 3, wn = wid >> 2;
    const int row0 = (swapxy ? blockIdx.y : blockIdx.x) * 128;
    const int col0 = (swapxy ? blockIdx.x : blockIdx.y) * BN;
    {   // batch offsets
        const int bz = blockIdx.z;
        Ah += (size_t)bz * astride;
        Bh += (size_t)bz * bstride;
        if (NPASS == 2) Bl += (size_t)bz * bstride;
        if (Cf) Cf += (size_t)bz * cstride;
        if (Ch) Ch += (size_t)bz * cstride;
        if (bias) bias += bz * biasstride;
        if (XCh) XCh += (size_t)bz * xcstride;
    }

    float acc[2][2*NP][4];
    #pragma unroll
    for (int i = 0; i < 2; i++)
        #pragma unroll
        for (int j = 0; j < 2*NP; j++)
            #pragma unroll
            for (int e = 0; e < 4; e++) acc[i][j][e] = 0.f;

    const int arow = wm*32 + (lane & 15);
    const uint32_t aoff = (uint32_t)arow*(RU*16) + ((lane >> 4) ? 16u : 0u);
    const int brow = wn*WN + (lane & 7) + ((lane >> 4) & 1)*8;
    const uint32_t boff = (uint32_t)(A16u*16) + (uint32_t)brow*(RU*16)
                          + (((lane >> 3) & 1) ? 16u : 0u);

    uint4 ra[NBA], rb[NBB];

    auto gload = [&](int c) {
        const int k0 = c * BK;
        #pragma unroll
        for (int t = 0; t < NBA; t++) {
            int i = tid + t*256;
            int r = i / (2*KR), kc = i % (2*KR);
            ra[t] = *(const uint4*)(Ah + (size_t)(row0 + r)*lda + k0 + kc*8);
        }
        #pragma unroll
        for (int t = 0; t < NBB; t++) {
            int i = tid + t*256;
            int mat = i / BU, u = i % BU, r = u / (2*KR), kc = u % (2*KR);
            rb[t] = *(const uint4*)((mat ? Bl : Bh) + (size_t)(col0 + r)*ldb + k0 + kc*8);
        }
    };
    auto sstore = [&](int st) {
        char* sb = smem + st * STAGE_BYTES;
        #pragma unroll
        for (int t = 0; t < NBA; t++) {
            int i = tid + t*256;
            int r = i / (2*KR), kc = i % (2*KR);
            *(uint4*)(sb + (uint32_t)(r*RU + kc)*16) = ra[t];
        }
        #pragma unroll
        for (int t = 0; t < NBB; t++) {
            int i = tid + t*256;
            int mat = i / BU, u = i % BU, r = u / (2*KR), kc = u % (2*KR);
            *(uint4*)(sb + (uint32_t)(A16u + mat*B16u + r*RU + kc)*16) = rb[t];
        }
    };

    const int nch = K / BK;
    gload(0);
    sstore(0);

    for (int c = 0; c < nch; c++) {
        if (c + 1 < nch) gload(c + 1);
        __syncthreads();

        const uint32_t sb = sbase + (uint32_t)(c & 1) * STAGE_BYTES;
        #pragma unroll
        for (int ks = 0; ks < KR; ks++) {
            uint32_t ahf[2][4];
            #pragma unroll
            for (int mi = 0; mi < 2; mi++)
                ldm4(ahf[mi], sb + aoff + ks*32 + (uint32_t)mi * (16*RU*16));
            uint32_t bhf[NP][4], blf[NP][4];
            #pragma unroll
            for (int np = 0; np < NP; np++) {
                uint32_t bd = sb + boff + ks*32 + (uint32_t)np * (16*RU*16);
                ldm4(bhf[np], bd);
                if (NPASS == 2) ldm4(blf[np], bd + B16u*16);
            }
            #pragma unroll
            for (int mi = 0; mi < 2; mi++)
                #pragma unroll
                for (int np = 0; np < NP; np++)
                    #pragma unroll
                    for (int hf = 0; hf < 2; hf++) {
                        int na = np*2 + hf;
                        mma16816(acc[mi][na], ahf[mi], bhf[np][2*hf], bhf[np][2*hf+1]);
                        if (NPASS == 2)
                            mma16816(acc[mi][na], ahf[mi], blf[np][2*hf], blf[np][2*hf+1]);
                    }
        }

        if (c + 1 < nch) sstore((c + 1) & 1);
    }

    // ---- epilogue
    float* smemf = (float*)smem;
    if (XCh || lng) __syncthreads();   // final-stage reads done before smem reuse

    const int lr = lane >> 2, lc = (lane & 3) * 2;
    #pragma unroll
    for (int mi = 0; mi < 2; mi++) {
        #pragma unroll
        for (int na = 0; na < 2*NP; na++) {
            int gr0 = row0 + wm*32 + mi*16 + lr;
            int gc0l = wn*WN + na*8 + lc;
            #pragma unroll
            for (int e = 0; e < 4; e++) {
                int gr = gr0 + (e >> 1) * 8;
                int gcl = gc0l + (e & 1);
                int gc = col0 + gcl;
                if (gc >= Nout) continue;
                float v = acc[mi][na][e];
                size_t ci = (size_t)gr * ldc + gc;
                if (flags & FLAG_T2)
                    v = 2.f*v - (__half2float(Xh[ci]) + __half2float(Xl[ci]));
                if (flags & FLAG_BIAS) v += bias[gc];
                if (flags & FLAG_RELU) v = fmaxf(v, 0.f);
                if (lng) { smemf[(gr - row0)*121 + gc] = v; continue; }
                if (Cf) Cf[ci] = v;
                if (Ch) Ch[ci] = __float2half_rn(v);
                if (XCh) smemf[gcl*132 + (gr - row0)] = v;
            }
        }
    }

    if (lng) {
        // fused residual + LayerNorm over this CTA's 128 rows (Nout cols)
        __syncthreads();
        for (int rr = 0; rr < 16; rr++) {
            int rl = wid*16 + rr;
            size_t m = (size_t)row0 + rl;
            float vals[4]; float s = 0.f;
            #pragma unroll
            for (int i = 0; i < 4; i++) {
                int d = lane + 32*i;
                float val = (d < Nout) ? (smemf[rl*121 + d] + lnx[m*DD + d]) : 0.f;
                vals[i] = val; s += val;
            }
            #pragma unroll
            for (int o = 16; o > 0; o >>= 1) s += __shfl_xor_sync(0xffffffffu, s, o);
            float mean = s * (1.f / DD);
            float vsum = 0.f;
            #pragma unroll
            for (int i = 0; i < 4; i++) {
                int d = lane + 32*i;
                if (d < Nout) { float df = vals[i] - mean; vsum += df*df; }
            }
            #pragma unroll
            for (int o = 16; o > 0; o >>= 1) vsum += __shfl_xor_sync(0xffffffffu, vsum, o);
            float inv = rsqrtf(vsum * (1.f / DD) + 1e-5f);
            #pragma unroll
            for (int i = 0; i < 4; i++) {
                int d = lane + 32*i;
                if (d < Nout) {
                    float o = (vals[i] - mean) * inv * lng[d] + lnb[d];
                    if (lnoutF) lnoutF[m*DD + d] = o;
                    if (lnoutH) lnoutH[m*128 + d] = __float2half_rn(o);
                }
            }
        }
        return;
    }

    if (XCh) {
        __syncthreads();
        for (int i = tid; i < BN*128; i += 256) {
            int gcl = i >> 7, grl = i & 127;
            int n = col0 + gcl;
            if (n >= Nout) continue;
            float v = smemf[gcl*132 + grl];
            int gr = row0 + grl;
            int bt = gr / DD, d = gr - bt*DD;
            size_t idx = ((size_t)bt*NN + n)*XK + xoff + d;
            XCh[idx] = __float2half_rn(v);
        }
    }
}

// ------------------------- graph learning -------------------------
__global__ void gk1(const float* __restrict__ w1, const float* __restrict__ w2,
                    const float* __restrict__ beta, const float* __restrict__ cw,
                    const float* __restrict__ cb, const float* __restrict__ adj) {
    int r = blockIdx.x, br = blockIdx.y;
    __shared__ float w1r[DD], w2r[DD];
    __shared__ float red[256];
    const float* W1 = w1 + (size_t)br*NN*DD;
    const float* W2 = w2 + (size_t)br*NN*DD;
    for (int i = threadIdx.x; i < DD; i += blockDim.x) { w1r[i] = W1[r*DD+i]; w2r[i] = W2[r*DD+i]; }
    __syncthreads();
    float cw0 = cw[br*2+0], cw1 = cw[br*2+1], cbv = cb[br];
    float mysum = 0.f;
    for (int c = threadIdx.x; c < NN; c += blockDim.x) {
        const float* w1c = W1 + c*DD;
        const float* w2c = W2 + c*DD;
        float d1 = 0.f, d2 = 0.f;
        for (int e = 0; e < DD; e++) { d1 += w1r[e]*w2c[e]; d2 += w2r[e]*w1c[e]; }
        float nw = d1 - d2;
        if (r == c) nw += beta[br*NN + r];
        nw = fmaxf(nw, 0.f);
        float ad = adj[r*NN + c];
        float gate = 1.f / (1.f + expf(-(cw0*nw + cw1*ad + cbv)));
        float a = gate*nw + (1.f - gate)*ad;
        g_A[(size_t)br*NN*NN + (size_t)r*NN + c] = a;
        mysum += a;
    }
    red[threadIdx.x] = mysum; __syncthreads();
    for (int s = 128; s > 0; s >>= 1) { if (threadIdx.x < s) red[threadIdx.x] += red[threadIdx.x+s]; __syncthreads(); }
    if (threadIdx.x == 0) g_rs0[br*NN + r] = red[0];
}
__global__ void gk2() {
    int r = blockIdx.x, br = blockIdx.y;
    __shared__ float red[256];
    float dr = rsqrtf(g_rs0[br*NN + r]);
    const float eps = 0.5f / (float)NN;
    float mysum = 0.f;
    for (int c = threadIdx.x; c < NN; c += blockDim.x) {
        float dc = rsqrtf(g_rs0[br*NN + c]);
        size_t idx = (size_t)br*NN*NN + (size_t)r*NN + c;
        float a = fmaxf(dr * g_A[idx] * dc - eps, 0.f);
        g_A[idx] = a; mysum += a;
    }
    red[threadIdx.x] = mysum; __syncthreads();
    for (int s = 128; s > 0; s >>= 1) { if (threadIdx.x < s) red[threadIdx.x] += red[threadIdx.x+s]; __syncthreads(); }
    if (threadIdx.x == 0) g_rs1[br*NN + r] = red[0];
}
__global__ void gk3() {
    int r = blockIdx.x, br = blockIdx.y;
    __shared__ float red[256];
    float dr = rsqrtf(g_rs1[br*NN + r]);
    float mysum = 0.f;
    for (int c = threadIdx.x; c < NN; c += blockDim.x) {
        float dc = rsqrtf(g_rs1[br*NN + c]);
        size_t idx = (size_t)br*NN*NN + (size_t)r*NN + c;
        float g = dr * g_A[idx] * dc;
        g_A[idx] = g; mysum += g;
    }
    red[threadIdx.x] = mysum; __syncthreads();
    for (int s = 128; s > 0; s >>= 1) { if (threadIdx.x < s) red[threadIdx.x] += red[threadIdx.x+s]; __syncthreads(); }
    if (threadIdx.x == 0) g_rs0[br*NN + r] = red[0];
}
__global__ void gk4() {
    int r = blockIdx.x, br = blockIdx.y;
    float er = rsqrtf(g_rs0[br*NN + r]);
    for (int c = threadIdx.x; c < NKP; c += blockDim.x) {
        float L = 0.f;
        if (c < NN) {
            float ec = rsqrtf(g_rs0[br*NN + c]);
            L = ((r == c) ? 1.f : 0.f) - er * g_A[(size_t)br*NN*NN + (size_t)r*NN + c] * ec;
        }
        g_Lh[(size_t)br*NKP*NKP + (size_t)r*NKP + c] = __float2half_rn(L);
    }
}

// ------------------------- layout / split kernels -------------------------
__global__ void xsplitT(const float* __restrict__ x) {
    __shared__ float s[64*121];
    int bt = blockIdx.x;
    for (int n0 = 0; n0 < NN; n0 += 64) {
        int nrows = (NN - n0 < 64) ? (NN - n0) : 64;
        for (int i = threadIdx.x; i < nrows*DD; i += 256) {
            int nn = i / DD, d = i - nn*DD;
            s[nn*121 + d] = x[((size_t)bt*NN + n0 + nn)*DD + d];
        }
        __syncthreads();
        for (int i = threadIdx.x; i < DD*64; i += 256) {
            int d = i >> 6, nn = i & 63;
            int n = n0 + nn;
            if (nn < nrows) {
                __half h, l; hsplit(s[nn*121 + d], h, l);
                size_t idx = ((size_t)bt*DD + d)*NKP + n;
                g_xth[idx] = h; g_xtl[idx] = l;
            }
        }
        __syncthreads();
    }
}
__global__ void pack_x(const float* __restrict__ x) {
    size_t r = blockIdx.x;
    int d = threadIdx.x;
    if (d < DD) {
        __half h = __float2half_rn(x[r*DD + d]);
        #pragma unroll
        for (int br = 0; br < 3; br++)
            g_xcath[(size_t)br*MTOK*XK + r*XK + d] = h;
    }
}
__global__ void wsplit(const float* __restrict__ src, __half* __restrict__ dh,
                       __half* __restrict__ dl, int K, int N, int ldk,
                       long src_bstride, long dst_bstride) {
    int n = blockIdx.x;
    int br = blockIdx.y;
    src += (size_t)br * src_bstride;
    dh  += (size_t)br * dst_bstride;
    if (dl) dl += (size_t)br * dst_bstride;
    for (int k = threadIdx.x; k < K; k += blockDim.x) {
        __half h, l; hsplit(src[(size_t)k*N + n], h, l);
        dh[(size_t)n*ldk + k] = h;
        if (dl) dl[(size_t)n*ldk + k] = l;
    }
}

// ------------------------- attention (fp16 in, fp16 out) -------------------
__global__ void attn_kernel(const __half* __restrict__ q, const __half* __restrict__ k,
                            const __half* __restrict__ v) {
    int bn = blockIdx.x;
    int b = bn / NN, n = bn % NN;
    __shared__ float qs[TT][DD], ks[TT][DD], vs[TT][DD];
    for (int i = threadIdx.x; i < TT*DD; i += blockDim.x) {
        int t = i / DD, d = i % DD;
        size_t gi = (((size_t)(b*TT + t))*NN + n)*DD + d;
        qs[t][d] = __half2float(q[gi]);
        ks[t][d] = __half2float(k[gi]);
        vs[t][d] = __half2float(v[gi]);
    }
    __syncthreads();
    int tid = threadIdx.x;
    if (tid < HH*TT) {
        int h = tid / TT, qi = tid % TT;
        const float scale = rsqrtf((float)HD);
        float s[TT]; float mx = -1e30f;
        #pragma unroll
        for (int j = 0; j < TT; j++) {
            float acc = 0.f;
            #pragma unroll
            for (int e = 0; e < HD; e++) acc += qs[qi][h*HD+e] * ks[j][h*HD+e];
            acc *= scale; s[j] = acc; mx = fmaxf(mx, acc);
        }
        float sum = 0.f;
        #pragma unroll
        for (int j = 0; j < TT; j++) { s[j] = expf(s[j]-mx); sum += s[j]; }
        float inv = 1.f / sum;
        size_t orow = ((size_t)(b*TT + qi))*NN + n;
        #pragma unroll
        for (int e = 0; e < HD; e++) {
            float acc = 0.f;
            #pragma unroll
            for (int j = 0; j < TT; j++) acc += s[j] * vs[j][h*HD+e];
            g_oah[orow*128 + h*HD + e] = __float2half_rn(acc * inv);
        }
    }
}

// ------------------------- launch -------------------------
extern "C" void kernel_launch(void* const* d_in, const int* in_sizes, int n_in,
                              void* d_out, int out_size) {
    const float* x       = (const float*)d_in[0];
    const float* adj     = (const float*)d_in[1];
    const float* gl_beta = (const float*)d_in[2];
    const float* gl_w1   = (const float*)d_in[3];
    const float* gl_w2   = (const float*)d_in[4];
    const float* gl_cw   = (const float*)d_in[5];
    const float* gl_cb   = (const float*)d_in[6];
    const float* cheb_w  = (const float*)d_in[7];
    const float* cheb_b  = (const float*)d_in[8];
    const float* out_w   = (const float*)d_in[9];
    const float* out_b   = (const float*)d_in[10];
    const float* ff_w1   = (const float*)d_in[11];
    const float* ff_b1   = (const float*)d_in[12];
    const float* ff_w2   = (const float*)d_in[13];
    const float* ff_b2   = (const float*)d_in[14];
    const float* ln1_g   = (const float*)d_in[15];
    const float* ln1_b   = (const float*)d_in[16];
    const float* ln2_g   = (const float*)d_in[17];
    const float* ln2_b   = (const float*)d_in[18];
    float* outp = (float*)d_out;

    const int SMEM128_2_32 = 61952;   // oproj+LN1: stages 61440, LN staging 61952
    const int SMEM128_1_64 = 73728;   // QKV/FFN1/FFN2 (LN staging 61952 fits)
    const int SMEM64_1_64  = 55296;   // spatial (scatter staging 33792 fits)
    cudaFuncSetAttribute(hmma_fp16<128,2,32>, cudaFuncAttributeMaxDynamicSharedMemorySize, SMEM128_2_32);
    cudaFuncSetAttribute(hmma_fp16<128,1,64>, cudaFuncAttributeMaxDynamicSharedMemorySize, SMEM128_1_64);
    cudaFuncSetAttribute(hmma_fp16<64,1,64>,  cudaFuncAttributeMaxDynamicSharedMemorySize, SMEM64_1_64);

    __half *pLh, *pxth, *pxtl, *pt1h;
    __half *pxch, *poah, *po1h, *phh, *pqkvh;
    __half *pwqh, *powh, *powl, *pw1h, *pw2h;
    float *pout1f;
    cudaGetSymbolAddress((void**)&pLh, g_Lh);
    cudaGetSymbolAddress((void**)&pxth, g_xth); cudaGetSymbolAddress((void**)&pxtl, g_xtl);
    cudaGetSymbolAddress((void**)&pt1h, g_t1h);
    cudaGetSymbolAddress((void**)&pxch, g_xcath);
    cudaGetSymbolAddress((void**)&poah, g_oah);
    cudaGetSymbolAddress((void**)&po1h, g_o1h);
    cudaGetSymbolAddress((void**)&phh, g_hidh);
    cudaGetSymbolAddress((void**)&pqkvh, g_qkvh);
    cudaGetSymbolAddress((void**)&pwqh, g_wqh);
    cudaGetSymbolAddress((void**)&powh, g_owh); cudaGetSymbolAddress((void**)&powl, g_owl);
    cudaGetSymbolAddress((void**)&pw1h, g_w1h);
    cudaGetSymbolAddress((void**)&pw2h, g_w2h);
    cudaGetSymbolAddress((void**)&pout1f, g_out1f);

    // graph learning
    dim3 gG(NN, 3);
    gk1<<<gG, 256>>>(gl_w1, gl_w2, gl_beta, gl_cw, gl_cb, adj);
    gk2<<<gG, 256>>>();
    gk3<<<gG, 256>>>();
    gk4<<<gG, 256>>>();

    // layout + weight prep
    xsplitT<<<BT, 256>>>(x);
    pack_x<<<MTOK, 128>>>(x);
    wsplit<<<dim3(120,3), 256>>>(cheb_w, pwqh, nullptr, 360, 120, XK, (long)360*120, (long)128*XK);
    wsplit<<<dim3(120,1), 256>>>(out_w, powh, powl, 120, 120, 128, 0, 0);
    wsplit<<<dim3(FF,1),  256>>>(ff_w1, pw1h, nullptr, 120, FF, 128, 0, 0);
    wsplit<<<dim3(120,1), 256>>>(ff_w2, pw2h, nullptr, FF, 120, FF, 0, 0);

    const long t1s = (long)MSP*NKP;
    const long xcs = (long)MTOK*XK;
    const long Ls  = (long)NKP*NKP;

    // batched spatial t1 = L_br @ x (1-pass, BK=64) -> t1_br + xcat_br[120..239]
    dim3 gsp(MSP/128, 3, 3);
    hmma_fp16<64,1,64><<<gsp, 256, SMEM64_1_64>>>(pxth, NKP, pLh, nullptr, NKP, NKP,
                                                  nullptr, pt1h, NKP, NN,
                                                  nullptr, 0, nullptr, nullptr,
                                                  pxch, 120,
                                                  0, Ls, t1s, 0, xcs, 0,
                                                  nullptr, nullptr, nullptr, nullptr, nullptr);
    // batched spatial t2 = 2*(L_br @ t1_br) - x (1-pass, BK=64) -> xcat_br[240..359]
    hmma_fp16<64,1,64><<<gsp, 256, SMEM64_1_64>>>(pt1h, NKP, pLh, nullptr, NKP, NKP,
                                                  nullptr, nullptr, NKP, NN,
                                                  nullptr, FLAG_T2, pxth, pxtl,
                                                  pxch, 240,
                                                  t1s, Ls, 0, 0, xcs, 0,
                                                  nullptr, nullptr, nullptr, nullptr, nullptr);

    // batched QKV (1-pass, BK=64) -> fp16 q/k/v
    dim3 gqkv(MTOK/128, 1, 3);
    hmma_fp16<128,1,64><<<gqkv, 256, SMEM128_1_64>>>(pxch, XK, pwqh, nullptr, XK, XK,
                                                     nullptr, pqkvh, DD, DD,
                                                     cheb_b, FLAG_BIAS | FLAG_RELU,
                                                     nullptr, nullptr, nullptr, 0,
                                                     xcs, (long)128*XK, (long)MTOK*DD, DD, 0, 0,
                                                     nullptr, nullptr, nullptr, nullptr, nullptr);

    attn_kernel<<<BB*NN, 128>>>(pqkvh, pqkvh + (size_t)MTOK*DD, pqkvh + (size_t)2*MTOK*DD);

    dim3 gch(MTOK/128, 1, 1);
    // output projection (2-pass, BK=32) + fused LN1: out1 = LN(x + oproj)
    hmma_fp16<128,2,32><<<gch, 256, SMEM128_2_32>>>(poah, 128, powh, powl, 128, 128,
                                                    nullptr, nullptr, DD, DD,
                                                    out_b, FLAG_BIAS, nullptr, nullptr,
                                                    nullptr, 0, 0, 0, 0, 0, 0, 0,
                                                    x, ln1_g, ln1_b, pout1f, po1h);

    // FFN1 (1-pass, BK=64) -> hidden fp16; swapped grid for A reuse
    dim3 gf1(FF/128, MTOK/128, 1);
    hmma_fp16<128,1,64><<<gf1, 256, SMEM128_1_64>>>(po1h, 128, pw1h, nullptr, 128, 128,
                                                    nullptr, phh, FF, FF,
                                                    ff_b1, FLAG_BIAS | FLAG_RELU, nullptr, nullptr,
                                                    nullptr, 0, 0, 0, 0, 0, 0, 1,
                                                    nullptr, nullptr, nullptr, nullptr, nullptr);
    // FFN2 (1-pass, BK=64) + fused LN2 -> final output
    hmma_fp16<128,1,64><<<gch, 256, SMEM128_1_64>>>(phh, FF, pw2h, nullptr, FF, FF,
                                                    nullptr, nullptr, DD, DD,
                                                    ff_b2, FLAG_BIAS, nullptr, nullptr,
                                                    nullptr, 0, 0, 0, 0, 0, 0, 0,
                                                    pout1f, ln2_g, ln2_b, outp, nullptr);
}